// round 1
// baseline (speedup 1.0000x reference)
#include <cuda_runtime.h>
#include <math.h>

#define NN 8192
#define KK 32
#define DD 64
#define DID 32
#define BSZ 4
#define TT 8
#define DSCAN 1024

#define NT 8            // nodes per block
#define ROWS 32         // NT * BSZ rows per block
#define S 257           // smem row stride (conflict-free)

// Persistent state (allocation-free scratch)
__device__ float g_h[BSZ * NN * DD];
__device__ float g_msgs[2][BSZ * NN * DD];
__device__ float g_wc[BSZ * NN * KK];
__device__ float g_ident[NN * DID];

__device__ __forceinline__ float sigf(float x) { return 1.0f / (1.0f + __expf(-x)); }

// Y[rows, Cout] = act(X[rows, Cin] @ W[Cin, Cout] + b). TC = cols per thread (Cout = 32*TC).
// Warp w -> rows 4w..4w+3 (broadcast smem reads), lane -> cols lane*TC (coalesced W reads).
// ACT: 0 = none, 1 = silu, 2 = tanh
template <int TC, int ACT>
__device__ __forceinline__ void gemm_tile(const float* Xs, int Cin,
                                          const float* __restrict__ W,
                                          const float* __restrict__ bias,
                                          float* Ys, int yoff) {
    const int Cout = TC * 32;
    const int w = threadIdx.x >> 5;
    const int lane = threadIdx.x & 31;
    const int r0 = w * 4;
    const int c0 = lane * TC;
    float acc[4][TC];
#pragma unroll
    for (int i = 0; i < 4; i++)
#pragma unroll
        for (int j = 0; j < TC; j++) acc[i][j] = 0.0f;

    const float* xb = Xs + r0 * S;
    for (int k = 0; k < Cin; k++) {
        float x0 = xb[k];
        float x1 = xb[S + k];
        float x2 = xb[2 * S + k];
        float x3 = xb[3 * S + k];
        const float* wr = W + (size_t)k * Cout + c0;
        float wv[TC];
        if (TC == 8) {
            float4 u = __ldg(reinterpret_cast<const float4*>(wr));
            float4 v = __ldg(reinterpret_cast<const float4*>(wr) + 1);
            wv[0] = u.x; wv[1] = u.y; wv[2] = u.z; wv[3] = u.w;
            wv[4] = v.x; wv[5] = v.y; wv[6] = v.z; wv[7] = v.w;
        } else {
            float2 u = __ldg(reinterpret_cast<const float2*>(wr));
            wv[0] = u.x; wv[1] = u.y;
        }
#pragma unroll
        for (int j = 0; j < TC; j++) {
            acc[0][j] = fmaf(x0, wv[j], acc[0][j]);
            acc[1][j] = fmaf(x1, wv[j], acc[1][j]);
            acc[2][j] = fmaf(x2, wv[j], acc[2][j]);
            acc[3][j] = fmaf(x3, wv[j], acc[3][j]);
        }
    }
#pragma unroll
    for (int i = 0; i < 4; i++) {
#pragma unroll
        for (int j = 0; j < TC; j++) {
            float v = acc[i][j] + __ldg(bias + c0 + j);
            if (ACT == 1) v = v * (1.0f / (1.0f + __expf(-v)));
            else if (ACT == 2) v = tanhf(v);
            Ys[(r0 + i) * S + yoff + c0 + j] = v;
        }
    }
}

// mod_out = X[32,256] @ dw2[256,65] + db2 -> Ys[:, 0:65]. lane -> row, warp -> col group.
__device__ __forceinline__ void gemm_mod2(const float* Xs, const float* __restrict__ W,
                                          const float* __restrict__ bias, float* Ys) {
    const int row = threadIdx.x & 31;
    const int q = threadIdx.x >> 5;  // 0..7
    float acc[9];
#pragma unroll
    for (int m = 0; m < 9; m++) acc[m] = 0.0f;
    const float* xb = Xs + row * S;
    for (int k = 0; k < 256; k++) {
        float x = xb[k];
        const float* wr = W + k * 65;
#pragma unroll
        for (int m = 0; m < 9; m++) {
            int c = q + m * 8;
            if (c < 65) acc[m] = fmaf(x, __ldg(wr + c), acc[m]);
        }
    }
#pragma unroll
    for (int m = 0; m < 9; m++) {
        int c = q + m * 8;
        if (c < 65) Ys[row * S + c] = acc[m] + __ldg(bias + c);
    }
}

__global__ void __launch_bounds__(256, 2) step_kernel(
    const float* __restrict__ cc, const float* __restrict__ hebb,
    const int* __restrict__ conn,
    const float* __restrict__ sw1, const float* __restrict__ sb1,
    const float* __restrict__ sw2, const float* __restrict__ sb2,
    const float* __restrict__ mw1, const float* __restrict__ mb1,
    const float* __restrict__ mw2, const float* __restrict__ mb2,
    const float* __restrict__ dw1, const float* __restrict__ db1,
    const float* __restrict__ dw2, const float* __restrict__ db2,
    float* __restrict__ out, int t, int p) {
    extern __shared__ float sm[];
    float* A = sm;                     // ROWS*S  (mod_in; later scratch)
    float* B = A + ROWS * S;           // ROWS*S  (hidden / state_in / msg_in)
    float* C = B + ROWS * S;           // ROWS*S  (mod_out / hidden)
    float* wk = C + ROWS * S;          // ROWS*KK sigmoid(w_conn)
    float* idn = wk + ROWS * KK;       // NT*DID  new identity
    float* dec = idn + NT * DID;       // ROWS decay
    int* idxs = (int*)(dec + ROWS);    // NT*KK neighbor indices

    const int tid = threadIdx.x;
    const int n0 = blockIdx.x * NT;

    // ---- Phase 0: neighbor indices + sigmoid(w_conn) + mod_in fills ----
    {
        int ln = tid >> 5, k = tid & 31;
        idxs[tid] = conn[(n0 + ln) * KK + k];
    }
    for (int i = tid; i < ROWS * KK; i += 256) {
        int r = i >> 5, k = i & 31, ln = r >> 2, b = r & 3;
        wk[i] = sigf(g_wc[((size_t)b * NN + n0 + ln) * KK + k]);
    }
    for (int i = tid; i < ROWS * KK; i += 256) {  // hebbian -> [0:32]
        int r = i >> 5, j = i & 31, ln = r >> 2, b = r & 3;
        A[r * S + j] = hebb[((size_t)b * NN + n0 + ln) * KK + j];
    }
    for (int i = tid; i < ROWS * DD; i += 256) {  // h -> [32:96]
        int r = i >> 6, d = i & 63, ln = r >> 2, b = r & 3;
        A[r * S + 32 + d] = g_h[((size_t)b * NN + n0 + ln) * DD + d];
    }
    for (int i = tid; i < ROWS * DID; i += 256) {  // ident -> [96:128]
        int r = i >> 5, j = i & 31, ln = r >> 2;
        A[r * S + 96 + j] = g_ident[(n0 + ln) * DID + j];
    }
    for (int i = tid; i < ROWS * DD; i += 256) {  // inject -> [192:256]
        int r = i >> 6, d = i & 63, ln = r >> 2, b = r & 3;
        int n = n0 + ln;
        A[r * S + 192 + d] = cc[((size_t)b * TT + t) * DSCAN + (n >> 9) * DD + d];
    }
    __syncthreads();

    // ---- received = sum_k sigmoid(w) * msgs[neighbor] -> [128:192] ----
    {
        const int sub = tid >> 6;  // = batch index of row
        const int d = tid & 63;
        const float* mp = g_msgs[p];
        for (int it = 0; it < NT; it++) {
            int r = it * 4 + sub;
            float acc = 0.0f;
#pragma unroll 8
            for (int k = 0; k < KK; k++) {
                int nb = idxs[it * KK + k];
                acc = fmaf(wk[r * KK + k], mp[((size_t)sub * NN + nb) * DD + d], acc);
            }
            A[r * S + 128 + d] = acc;
        }
    }
    __syncthreads();

    // ---- mod MLP ----
    gemm_tile<8, 1>(A, 256, dw1, db1, B, 0);
    __syncthreads();
    gemm_mod2(B, dw2, db2, C);
    __syncthreads();

    // ---- w_new, decay, identity update (batch mean) ----
    for (int i = tid; i < ROWS * KK; i += 256) {
        int r = i >> 5, k = i & 31, ln = r >> 2, b = r & 3;
        g_wc[((size_t)b * NN + n0 + ln) * KK + k] = C[r * S + k];
    }
    if (tid < ROWS) dec[tid] = sigf(C[tid * S + 32]);
    if (tid < NT * DID) {
        int ln = tid >> 5, j = tid & 31;
        float v = g_ident[(n0 + ln) * DID + j] +
                  0.25f * (C[(ln * 4 + 0) * S + 33 + j] + C[(ln * 4 + 1) * S + 33 + j] +
                           C[(ln * 4 + 2) * S + 33 + j] + C[(ln * 4 + 3) * S + 33 + j]);
        idn[tid] = v;
        g_ident[(n0 + ln) * DID + j] = v;
    }
    __syncthreads();

    // ---- build state_in [received, inject, h, ide2] into B ----
    for (int i = tid; i < ROWS * 224; i += 256) {
        int r = i / 224, c = i - r * 224;
        float v;
        if (c < 64) v = A[r * S + 128 + c];
        else if (c < 128) v = A[r * S + 192 + (c - 64)];
        else if (c < 192) v = A[r * S + 32 + (c - 128)];
        else v = idn[(r >> 2) * DID + (c - 192)];
        B[r * S + c] = v;
    }
    __syncthreads();

    // ---- state MLP ----
    gemm_tile<8, 1>(B, 224, sw1, sb1, C, 0);
    __syncthreads();
    gemm_tile<2, 2>(C, 256, sw2, sb2, A, 96);  // tanh -> A[:,96:160]
    __syncthreads();

    // ---- h_new = decay*h + (1-decay)*tanh; write out + start msg_in ----
    for (int i = tid; i < ROWS * DD; i += 256) {
        int r = i >> 6, d = i & 63, ln = r >> 2, b = r & 3;
        float de = dec[r];
        float hn = de * A[r * S + 32 + d] + (1.0f - de) * A[r * S + 96 + d];
        g_h[((size_t)b * NN + n0 + ln) * DD + d] = hn;
        out[(((size_t)b * TT + t) * NN + n0 + ln) * DD + d] = hn;
        B[r * S + d] = hn;
    }
    for (int i = tid; i < ROWS * DID; i += 256) {
        int r = i >> 5, j = i & 31;
        B[r * S + 64 + j] = idn[(r >> 2) * DID + j];
    }
    __syncthreads();

    // ---- msg MLP ----
    gemm_tile<8, 1>(B, 96, mw1, mb1, C, 0);
    __syncthreads();
    gemm_tile<2, 2>(C, 256, mw2, mb2, A, 0);  // tanh -> A[:,0:64]
    __syncthreads();
    for (int i = tid; i < ROWS * DD; i += 256) {
        int r = i >> 6, d = i & 63, ln = r >> 2, b = r & 3;
        g_msgs[p ^ 1][((size_t)b * NN + n0 + ln) * DD + d] = A[r * S + d];
    }
}

__global__ void init_kernel(const float* __restrict__ h0, const float* __restrict__ m0,
                            const float* __restrict__ w0, const float* __restrict__ id0) {
    size_t i = (size_t)blockIdx.x * blockDim.x + threadIdx.x;
    if (i < (size_t)BSZ * NN * DD) {
        g_h[i] = h0[i];
        g_msgs[0][i] = m0[i];
    }
    if (i < (size_t)BSZ * NN * KK) g_wc[i] = w0[i];
    if (i < (size_t)NN * DID) g_ident[i] = id0[i];
}

#define SMEM_BYTES ((3 * ROWS * S + ROWS * KK + NT * DID + ROWS) * 4 + NT * KK * 4)

extern "C" void kernel_launch(void* const* d_in, const int* in_sizes, int n_in,
                              void* d_out, int out_size) {
    const float* cc   = (const float*)d_in[0];
    const float* h0   = (const float*)d_in[1];
    const float* m0   = (const float*)d_in[2];
    const float* w0   = (const float*)d_in[3];
    const float* hebb = (const float*)d_in[4];
    const float* id0  = (const float*)d_in[5];
    const float* sw1  = (const float*)d_in[6];
    const float* sb1  = (const float*)d_in[7];
    const float* sw2  = (const float*)d_in[8];
    const float* sb2  = (const float*)d_in[9];
    const float* mw1  = (const float*)d_in[10];
    const float* mb1  = (const float*)d_in[11];
    const float* mw2  = (const float*)d_in[12];
    const float* mb2  = (const float*)d_in[13];
    const float* dw1  = (const float*)d_in[14];
    const float* db1  = (const float*)d_in[15];
    const float* dw2  = (const float*)d_in[16];
    const float* db2  = (const float*)d_in[17];
    const int* conn   = (const int*)d_in[18];
    float* out = (float*)d_out;

    cudaFuncSetAttribute(step_kernel, cudaFuncAttributeMaxDynamicSharedMemorySize,
                         SMEM_BYTES);

    init_kernel<<<(BSZ * NN * DD + 255) / 256, 256>>>(h0, m0, w0, id0);
    for (int t = 0; t < TT; t++) {
        step_kernel<<<NN / NT, 256, SMEM_BYTES>>>(
            cc, hebb, conn, sw1, sb1, sw2, sb2, mw1, mb1, mw2, mb2,
            dw1, db1, dw2, db2, out, t, t & 1);
    }
}

// round 2
// speedup vs baseline: 1.2915x; 1.2915x over previous
#include <cuda_runtime.h>
#include <math.h>

#define NN 8192
#define KK 32
#define DD 64
#define DID 32
#define BSZ 4
#define TT 8
#define DSCAN 1024

#define NT 8            // nodes per block
#define ROWS 32         // NT * BSZ rows per block
#define S 260           // smem row stride (16B-aligned rows, conflict-free broadcast)

typedef unsigned long long ull;

// Persistent state (allocation-free scratch)
__device__ float g_h[BSZ * NN * DD];
__device__ float g_msgs[2][BSZ * NN * DD];
__device__ float g_wc[BSZ * NN * KK];
__device__ float g_ident[NN * DID];
__device__ float g_dw2p[256 * 128];   // dw2 padded 65 -> 128 cols
__device__ float g_db2p[128];

__device__ __forceinline__ float sigf(float x) { return 1.0f / (1.0f + __expf(-x)); }

__device__ __forceinline__ ull ffma2(ull a, ull b, ull c) {
    ull d;
    asm("fma.rn.f32x2 %0, %1, %2, %3;" : "=l"(d) : "l"(a), "l"(b), "l"(c));
    return d;
}
__device__ __forceinline__ ull pack2(float x) {
    ull p;
    unsigned u = __float_as_uint(x);
    asm("mov.b64 %0, {%1, %2};" : "=l"(p) : "r"(u), "r"(u));
    return p;
}
__device__ __forceinline__ float2 unpack2(ull p) {
    unsigned lo, hi;
    asm("mov.b64 {%0, %1}, %2;" : "=r"(lo), "=r"(hi) : "l"(p));
    return make_float2(__uint_as_float(lo), __uint_as_float(hi));
}

// Y[rows, 64*TCH] = act(X[rows, CIN] @ W[CIN, LDW] + b), packed f32x2 columns.
// Warp w -> rows 4w..4w+3 (broadcast smem reads), lane -> col pairs at c0 = lane*2*TCH.
// ACT: 0 = none, 1 = silu, 2 = tanh
template <int TCH, int ACT, int CIN, int LDW>
__device__ __forceinline__ void gemm2(const float* Xs,
                                      const float* __restrict__ W,
                                      const float* __restrict__ bias,
                                      float* Ys, int yoff) {
    const int w = threadIdx.x >> 5;
    const int lane = threadIdx.x & 31;
    const int r0 = w * 4;
    const int c0 = lane * (2 * TCH);
    ull acc[4][TCH];
#pragma unroll
    for (int i = 0; i < 4; i++)
#pragma unroll
        for (int j = 0; j < TCH; j++) acc[i][j] = 0ull;

    const float* xb = Xs + r0 * S;
#pragma unroll 2
    for (int k0 = 0; k0 < CIN; k0 += 4) {
        float4 xv0 = *reinterpret_cast<const float4*>(xb + k0);
        float4 xv1 = *reinterpret_cast<const float4*>(xb + S + k0);
        float4 xv2 = *reinterpret_cast<const float4*>(xb + 2 * S + k0);
        float4 xv3 = *reinterpret_cast<const float4*>(xb + 3 * S + k0);
        float xa0[4] = {xv0.x, xv0.y, xv0.z, xv0.w};
        float xa1[4] = {xv1.x, xv1.y, xv1.z, xv1.w};
        float xa2[4] = {xv2.x, xv2.y, xv2.z, xv2.w};
        float xa3[4] = {xv3.x, xv3.y, xv3.z, xv3.w};
#pragma unroll
        for (int kk = 0; kk < 4; kk++) {
            ull wv[TCH];
            const float* wr = W + (size_t)(k0 + kk) * LDW + c0;
            if (TCH == 4) {
                ulonglong2 q0 = __ldg(reinterpret_cast<const ulonglong2*>(wr));
                ulonglong2 q1 = __ldg(reinterpret_cast<const ulonglong2*>(wr) + 1);
                wv[0] = q0.x; wv[1] = q0.y; wv[2] = q1.x; wv[3] = q1.y;
            } else if (TCH == 2) {
                ulonglong2 q0 = __ldg(reinterpret_cast<const ulonglong2*>(wr));
                wv[0] = q0.x; wv[1] = q0.y;
            } else {
                wv[0] = __ldg(reinterpret_cast<const ull*>(wr));
            }
            ull px0 = pack2(xa0[kk]);
            ull px1 = pack2(xa1[kk]);
            ull px2 = pack2(xa2[kk]);
            ull px3 = pack2(xa3[kk]);
#pragma unroll
            for (int j = 0; j < TCH; j++) {
                acc[0][j] = ffma2(px0, wv[j], acc[0][j]);
                acc[1][j] = ffma2(px1, wv[j], acc[1][j]);
                acc[2][j] = ffma2(px2, wv[j], acc[2][j]);
                acc[3][j] = ffma2(px3, wv[j], acc[3][j]);
            }
        }
    }
#pragma unroll
    for (int i = 0; i < 4; i++) {
#pragma unroll
        for (int j = 0; j < TCH; j++) {
            float2 v = unpack2(acc[i][j]);
            int c = c0 + 2 * j;
            v.x += __ldg(bias + c);
            v.y += __ldg(bias + c + 1);
            if (ACT == 1) {
                v.x = v.x * (1.0f / (1.0f + __expf(-v.x)));
                v.y = v.y * (1.0f / (1.0f + __expf(-v.y)));
            } else if (ACT == 2) {
                v.x = tanhf(v.x);
                v.y = tanhf(v.y);
            }
            Ys[(r0 + i) * S + yoff + c] = v.x;
            Ys[(r0 + i) * S + yoff + c + 1] = v.y;
        }
    }
}

__global__ void __launch_bounds__(256, 2) step_kernel(
    const float* __restrict__ cc, const float* __restrict__ hebb,
    const int* __restrict__ conn,
    const float* __restrict__ sw1, const float* __restrict__ sb1,
    const float* __restrict__ sw2, const float* __restrict__ sb2,
    const float* __restrict__ mw1, const float* __restrict__ mb1,
    const float* __restrict__ mw2, const float* __restrict__ mb2,
    const float* __restrict__ dw1, const float* __restrict__ db1,
    float* __restrict__ out, int t, int p) {
    extern __shared__ float sm[];
    float* A = sm;                     // ROWS*S  (mod_in; later scratch)
    float* B = A + ROWS * S;           // ROWS*S  (hidden / state_in / msg_in)
    float* C = B + ROWS * S;           // ROWS*S  (mod_out / hidden)
    float* wk = C + ROWS * S;          // ROWS*KK sigmoid(w_conn)
    float* idn = wk + ROWS * KK;       // NT*DID  new identity
    float* dec = idn + NT * DID;       // ROWS decay
    int* idxs = (int*)(dec + ROWS);    // NT*KK neighbor indices

    const int tid = threadIdx.x;
    const int n0 = blockIdx.x * NT;

    // ---- Phase 0: neighbor indices + sigmoid(w_conn) + mod_in fills ----
    {
        int ln = tid >> 5, k = tid & 31;
        idxs[tid] = conn[(n0 + ln) * KK + k];
    }
    for (int i = tid; i < ROWS * KK; i += 256) {
        int r = i >> 5, k = i & 31, ln = r >> 2, b = r & 3;
        wk[i] = sigf(g_wc[((size_t)b * NN + n0 + ln) * KK + k]);
    }
    for (int i = tid; i < ROWS * KK; i += 256) {  // hebbian -> [0:32]
        int r = i >> 5, j = i & 31, ln = r >> 2, b = r & 3;
        A[r * S + j] = hebb[((size_t)b * NN + n0 + ln) * KK + j];
    }
    for (int i = tid; i < ROWS * DD; i += 256) {  // h -> [32:96]
        int r = i >> 6, d = i & 63, ln = r >> 2, b = r & 3;
        A[r * S + 32 + d] = g_h[((size_t)b * NN + n0 + ln) * DD + d];
    }
    for (int i = tid; i < ROWS * DID; i += 256) {  // ident -> [96:128]
        int r = i >> 5, j = i & 31, ln = r >> 2;
        A[r * S + 96 + j] = g_ident[(n0 + ln) * DID + j];
    }
    for (int i = tid; i < ROWS * DD; i += 256) {  // inject -> [192:256]
        int r = i >> 6, d = i & 63, ln = r >> 2, b = r & 3;
        int n = n0 + ln;
        A[r * S + 192 + d] = cc[((size_t)b * TT + t) * DSCAN + (n >> 9) * DD + d];
    }
    __syncthreads();

    // ---- received = sum_k sigmoid(w) * msgs[neighbor] -> [128:192] ----
    {
        const int sub = tid >> 6;  // = batch index of row
        const int d = tid & 63;
        const float* mp = g_msgs[p];
        for (int it = 0; it < NT; it++) {
            int r = it * 4 + sub;
            float acc = 0.0f;
#pragma unroll 8
            for (int k = 0; k < KK; k++) {
                int nb = idxs[it * KK + k];
                acc = fmaf(wk[r * KK + k], mp[((size_t)sub * NN + nb) * DD + d], acc);
            }
            A[r * S + 128 + d] = acc;
        }
    }
    __syncthreads();

    // ---- mod MLP ----
    gemm2<4, 1, 256, 256>(A, dw1, db1, B, 0);
    __syncthreads();
    gemm2<2, 0, 256, 128>(B, g_dw2p, g_db2p, C, 0);
    __syncthreads();

    // ---- w_new, decay, identity update (batch mean) ----
    for (int i = tid; i < ROWS * KK; i += 256) {
        int r = i >> 5, k = i & 31, ln = r >> 2, b = r & 3;
        g_wc[((size_t)b * NN + n0 + ln) * KK + k] = C[r * S + k];
    }
    if (tid < ROWS) dec[tid] = sigf(C[tid * S + 32]);
    if (tid < NT * DID) {
        int ln = tid >> 5, j = tid & 31;
        float v = g_ident[(n0 + ln) * DID + j] +
                  0.25f * (C[(ln * 4 + 0) * S + 33 + j] + C[(ln * 4 + 1) * S + 33 + j] +
                           C[(ln * 4 + 2) * S + 33 + j] + C[(ln * 4 + 3) * S + 33 + j]);
        idn[tid] = v;
        g_ident[(n0 + ln) * DID + j] = v;
    }
    __syncthreads();

    // ---- build state_in [received, inject, h, ide2] into B ----
    for (int i = tid; i < ROWS * 224; i += 256) {
        int r = i / 224, c = i - r * 224;
        float v;
        if (c < 64) v = A[r * S + 128 + c];
        else if (c < 128) v = A[r * S + 192 + (c - 64)];
        else if (c < 192) v = A[r * S + 32 + (c - 128)];
        else v = idn[(r >> 2) * DID + (c - 192)];
        B[r * S + c] = v;
    }
    __syncthreads();

    // ---- state MLP ----
    gemm2<4, 1, 224, 256>(B, sw1, sb1, C, 0);
    __syncthreads();
    gemm2<1, 2, 256, 64>(C, sw2, sb2, A, 96);  // tanh -> A[:,96:160]
    __syncthreads();

    // ---- h_new = decay*h + (1-decay)*tanh; write out + start msg_in ----
    for (int i = tid; i < ROWS * DD; i += 256) {
        int r = i >> 6, d = i & 63, ln = r >> 2, b = r & 3;
        float de = dec[r];
        float hn = de * A[r * S + 32 + d] + (1.0f - de) * A[r * S + 96 + d];
        g_h[((size_t)b * NN + n0 + ln) * DD + d] = hn;
        out[(((size_t)b * TT + t) * NN + n0 + ln) * DD + d] = hn;
        B[r * S + d] = hn;
    }
    for (int i = tid; i < ROWS * DID; i += 256) {
        int r = i >> 5, j = i & 31;
        B[r * S + 64 + j] = idn[(r >> 2) * DID + j];
    }
    __syncthreads();

    // ---- msg MLP ----
    gemm2<4, 1, 96, 256>(B, mw1, mb1, C, 0);
    __syncthreads();
    gemm2<1, 2, 256, 64>(C, mw2, mb2, A, 0);  // tanh -> A[:,0:64]
    __syncthreads();
    for (int i = tid; i < ROWS * DD; i += 256) {
        int r = i >> 6, d = i & 63, ln = r >> 2, b = r & 3;
        g_msgs[p ^ 1][((size_t)b * NN + n0 + ln) * DD + d] = A[r * S + d];
    }
}

__global__ void init_kernel(const float* __restrict__ h0, const float* __restrict__ m0,
                            const float* __restrict__ w0, const float* __restrict__ id0,
                            const float* __restrict__ dw2, const float* __restrict__ db2) {
    size_t i = (size_t)blockIdx.x * blockDim.x + threadIdx.x;
    if (i < (size_t)BSZ * NN * DD) {
        g_h[i] = h0[i];
        g_msgs[0][i] = m0[i];
    }
    if (i < (size_t)BSZ * NN * KK) g_wc[i] = w0[i];
    if (i < (size_t)NN * DID) g_ident[i] = id0[i];
    if (i < 256 * 128) {
        int r = (int)i >> 7, c = (int)i & 127;
        g_dw2p[i] = (c < 65) ? dw2[r * 65 + c] : 0.0f;
    }
    if (i < 128) g_db2p[i] = (i < 65) ? db2[i] : 0.0f;
}

#define SMEM_BYTES ((3 * ROWS * S + ROWS * KK + NT * DID + ROWS) * 4 + NT * KK * 4)

extern "C" void kernel_launch(void* const* d_in, const int* in_sizes, int n_in,
                              void* d_out, int out_size) {
    const float* cc   = (const float*)d_in[0];
    const float* h0   = (const float*)d_in[1];
    const float* m0   = (const float*)d_in[2];
    const float* w0   = (const float*)d_in[3];
    const float* hebb = (const float*)d_in[4];
    const float* id0  = (const float*)d_in[5];
    const float* sw1  = (const float*)d_in[6];
    const float* sb1  = (const float*)d_in[7];
    const float* sw2  = (const float*)d_in[8];
    const float* sb2  = (const float*)d_in[9];
    const float* mw1  = (const float*)d_in[10];
    const float* mb1  = (const float*)d_in[11];
    const float* mw2  = (const float*)d_in[12];
    const float* mb2  = (const float*)d_in[13];
    const float* dw1  = (const float*)d_in[14];
    const float* db1  = (const float*)d_in[15];
    const float* dw2  = (const float*)d_in[16];
    const float* db2  = (const float*)d_in[17];
    const int* conn   = (const int*)d_in[18];
    float* out = (float*)d_out;

    cudaFuncSetAttribute(step_kernel, cudaFuncAttributeMaxDynamicSharedMemorySize,
                         SMEM_BYTES);

    init_kernel<<<(BSZ * NN * DD + 255) / 256, 256>>>(h0, m0, w0, id0, dw2, db2);
    for (int t = 0; t < TT; t++) {
        step_kernel<<<NN / NT, 256, SMEM_BYTES>>>(
            cc, hebb, conn, sw1, sb1, sw2, sb2, mw1, mb1, mw2, mb2,
            dw1, db1, out, t, t & 1);
    }
}